// round 3
// baseline (speedup 1.0000x reference)
#include <cuda_runtime.h>

// ---------------------------------------------------------------------------
// Fused BasicBlockA:
//   w1 = (weight1*mask0 + softplus(center1)*mask1) * mask   (same for w2)
//   h  = elu(conv(x, w1) + bias1)        [B, 16*3, 128,128]  (kept in SMEM)
//   h2 = grouped_conv(h, w2, groups=16)
//   out = mean_L(h2) + res*(res>0)*x
//
// Mask structure (K=3, mid=1): row ky=2 fully zero; at ky=1 only kx=0 (all j)
// and kx=1 (j<=i; j==i uses softplus(center)). => 42 live taps per pixel/stage.
// Weights are pre-masked+compacted into [stage][latent][44] by prep_kernel.
//
// NOTE: stage-2 conv pads h with ZEROS outside the image — halo h pixels that
// fall outside [0,128)^2 must be 0, not elu(bias + partial conv).
// ---------------------------------------------------------------------------

#define L_DIM 16
#define WSLOT 44          // 42 live taps, padded to 44 for float4 loads
#define TX 32
#define TY 8
#define XS_H 10           // x tile rows: gy0-2 .. gy0+7  (only ky=0,1 used)
#define XS_W 36           // x tile cols: gx0-2 .. gx0+33
#define HS_H 9            // h tile rows: gy0-1 .. gy0+7
#define HS_W 34           // h tile cols: gx0-1 .. gx0+32

__device__ float g_wc[2 * L_DIM * WSLOT];

__device__ __forceinline__ float softplus_f(float v) {
    // numerically stable: max(v,0) + log1p(exp(-|v|))
    return fmaxf(v, 0.f) + log1pf(expf(-fabsf(v)));
}

// Precompute masked+compacted weights. One thread per (stage, latent).
__global__ void prep_kernel(const float* __restrict__ w1, const float* __restrict__ c1,
                            const float* __restrict__ w2, const float* __restrict__ c2) {
    int t = threadIdx.x;
    if (t >= 2 * L_DIM) return;
    int stage = t >> 4;
    int l = t & 15;
    const float* W = stage ? w2 : w1;
    const float* C = stage ? c2 : c1;
    float* dst = g_wc + t * WSLOT;
    int s = 0;
    for (int i = 0; i < 3; i++) {
        for (int j = 0; j < 3; j++) {
            int base = ((l * 3 + i) * 3 + j) * 9;   // [l,i,j,0,0]
            // ky = 0: kx = 0,1,2
            for (int kx = 0; kx < 3; kx++) dst[s++] = W[base + kx];
            // ky = 1, kx = 0
            dst[s++] = W[base + 3];
            // ky = 1, kx = 1 : only for j<=i ; j==i uses softplus(center)
            if (j <= i) {
                dst[s++] = (j == i) ? softplus_f(C[base + 4]) : W[base + 4];
            }
        }
    }
    dst[42] = 0.f;
    dst[43] = 0.f;
}

// 42-tap masked conv: accumulate into a[0..2]. Tap order MUST match prep_kernel.
template <typename F>
__device__ __forceinline__ void conv_taps(const float (&w)[WSLOT], float a[3], F src) {
    int s = 0;
#pragma unroll
    for (int i = 0; i < 3; i++) {
#pragma unroll
        for (int j = 0; j < 3; j++) {
#pragma unroll
            for (int kx = 0; kx < 3; kx++) { a[i] = fmaf(w[s], src(j, 0, kx), a[i]); s++; }
            a[i] = fmaf(w[s], src(j, 1, 0), a[i]); s++;
            if (j <= i) { a[i] = fmaf(w[s], src(j, 1, 1), a[i]); s++; }
        }
    }
}

__global__ __launch_bounds__(256)
void fused_kernel(const float* __restrict__ x, const float* __restrict__ bias1,
                  const float* __restrict__ res, float* __restrict__ out) {
    __shared__ float xs[3][XS_H][XS_W];
    __shared__ float hs[3][HS_H][HS_W];
    __shared__ alignas(16) float sw[2 * L_DIM * WSLOT];
    __shared__ float sb[L_DIM * 3];

    const int tid = threadIdx.x;
    const int b   = blockIdx.z;
    const int gy0 = blockIdx.y * TY;
    const int gx0 = blockIdx.x * TX;

    // stage weights + bias into SMEM
    for (int q = tid; q < 2 * L_DIM * WSLOT; q += 256) sw[q] = g_wc[q];
    if (tid < L_DIM * 3) sb[tid] = bias1[tid];

    // x tile with halo (zero-padded at image borders)
    const float* xb = x + (size_t)b * 3 * 128 * 128;
    for (int q = tid; q < 3 * XS_H * XS_W; q += 256) {
        int c  = q / (XS_H * XS_W);
        int r  = (q / XS_W) % XS_H;
        int cc = q % XS_W;
        int gy = gy0 - 2 + r;
        int gx = gx0 - 2 + cc;
        float v = 0.f;
        if ((unsigned)gy < 128u && (unsigned)gx < 128u)
            v = xb[(c * 128 + gy) * 128 + gx];
        xs[c][r][cc] = v;
    }
    __syncthreads();

    const int tx = tid & 31;
    const int ty = tid >> 5;
    float acc[3] = {0.f, 0.f, 0.f};

    for (int l = 0; l < L_DIM; l++) {
        alignas(16) float w[WSLOT];
        // stage-1 weights -> registers via float4 broadcasts
        {
            const float4* p = (const float4*)(sw + l * WSLOT);
#pragma unroll
            for (int q = 0; q < WSLOT / 4; q++) ((float4*)w)[q] = p[q];
        }
        const float b0 = sb[l * 3 + 0], b1 = sb[l * 3 + 1], b2 = sb[l * 3 + 2];

        // stage 1: h tile (with halo 1) = elu(conv(x) + bias); 0 outside image
#pragma unroll
        for (int it = 0; it < 2; it++) {
            int p = tid + it * 256;
            if (p < HS_H * HS_W) {
                int yy = p / HS_W;
                int xx = p % HS_W;
                int gy = gy0 - 1 + yy;
                int gx = gx0 - 1 + xx;
                bool inside = ((unsigned)gy < 128u) && ((unsigned)gx < 128u);
                float a[3] = {b0, b1, b2};
                conv_taps(w, a, [&](int j, int ky, int kx) {
                    return xs[j][yy + ky][xx + kx];
                });
#pragma unroll
                for (int i = 0; i < 3; i++) {
                    float v = a[i];
                    v = (v > 0.f) ? v : (__expf(v) - 1.f);
                    hs[i][yy][xx] = inside ? v : 0.f;
                }
            }
        }
        __syncthreads();

        // stage-2 weights
        {
            const float4* p = (const float4*)(sw + (L_DIM + l) * WSLOT);
#pragma unroll
            for (int q = 0; q < WSLOT / 4; q++) ((float4*)w)[q] = p[q];
        }
        float a[3] = {0.f, 0.f, 0.f};
        conv_taps(w, a, [&](int j, int ky, int kx) {
            return hs[j][ty + ky][tx + kx];
        });
        acc[0] += a[0];
        acc[1] += a[1];
        acc[2] += a[2];
        __syncthreads();   // before hs is overwritten next latent
    }

    // mean over latents + gated residual
    const float r = res[0];
    const float g = (r > 0.f) ? r : 0.f;
    const int gy = gy0 + ty, gx = gx0 + tx;
    float* ob = out + (size_t)b * 3 * 128 * 128;
#pragma unroll
    for (int i = 0; i < 3; i++) {
        ob[(i * 128 + gy) * 128 + gx] =
            acc[i] * (1.f / 16.f) + g * xs[i][ty + 2][tx + 2];
    }
}

extern "C" void kernel_launch(void* const* d_in, const int* in_sizes, int n_in,
                              void* d_out, int out_size) {
    const float* x  = (const float*)d_in[0];
    const float* w1 = (const float*)d_in[1];
    const float* c1 = (const float*)d_in[2];
    const float* b1 = (const float*)d_in[3];
    const float* w2 = (const float*)d_in[4];
    const float* c2 = (const float*)d_in[5];
    const float* rs = (const float*)d_in[6];
    (void)in_sizes; (void)n_in; (void)out_size;

    prep_kernel<<<1, 32>>>(w1, c1, w2, c2);

    dim3 grid(128 / TX, 128 / TY, 64);
    fused_kernel<<<grid, 256>>>(x, b1, rs, (float*)d_out);
}